// round 1
// baseline (speedup 1.0000x reference)
#include <cuda_runtime.h>
#include <cuda_bf16.h>
#include <math.h>

// ---------------- Problem constants ----------------
#define BATCH    2
#define SEQ      512
#define D_MODEL  1024
#define D_INNER  2048
#define D_STATE  16
#define DT_RANK  64
#define N_LAYERS 4
#define MROWS    (BATCH * SEQ)          // 1024
#define XDBL_N   (DT_RANK + 2 * D_STATE) // 96
#define SPLITK_XPROJ 8

// ---------------- Scratch (__device__ globals; no allocation allowed) ----------------
__device__ float g_x0[MROWS * D_MODEL];
__device__ float g_x1[MROWS * D_MODEL];
__device__ float g_xz[MROWS * 2 * D_INNER];
__device__ float g_xa[MROWS * D_INNER];
__device__ float g_xdbl[MROWS * XDBL_N];
__device__ float g_xdbl_part[SPLITK_XPROJ * MROWS * XDBL_N];
__device__ float g_dt[MROWS * D_INNER];
__device__ float g_y[MROWS * D_INNER];

// ---------------- Prologue: x = pe + cond ----------------
__global__ void prologue_kernel(const float* __restrict__ condition,
                                const float* __restrict__ pe,
                                const float* __restrict__ to_cond_w,
                                const float* __restrict__ to_cond_b,
                                float* __restrict__ x)
{
    int idx = blockIdx.x * blockDim.x + threadIdx.x;   // over BATCH*SEQ*D_MODEL
    if (idx >= MROWS * D_MODEL) return;
    int d = idx % D_MODEL;
    int l = (idx / D_MODEL) % SEQ;
    int b = idx / (D_MODEL * SEQ);
    float cond = condition[b] * to_cond_w[d] + to_cond_b[d];
    x[idx] = pe[l * D_MODEL + d] + cond;
}

// ---------------- Generic NT GEMM:  C[m,n] = sum_k A[m*lda+k] * W[n*K+k]  ----------------
// EPI: 0 = none, 1 = add bias[n] then softplus
template<int BM, int BN, int BK, int TM, int TN, int EPI>
__global__ void gemm_nt(const float* __restrict__ A,
                        const float* __restrict__ W,
                        const float* __restrict__ bias,
                        float* __restrict__ C,
                        int M, int N, int K, int lda, int ldc)
{
    constexpr int TX = BN / TN;
    constexpr int TY = BM / TM;
    constexpr int NT = TX * TY;
    constexpr int KV = BK / 4;

    __shared__ float As[BK][BM + 4];
    __shared__ float Bs[BK][BN + 4];

    const int tid = threadIdx.x;
    const int tx  = tid % TX;
    const int ty  = tid / TX;
    const int n0  = blockIdx.x * BN;
    const int m0  = blockIdx.y * BM;

    // split-K support via gridDim.z (partial outputs stacked along z)
    const int kChunk = K / gridDim.z;
    const int kBase  = blockIdx.z * kChunk;
    C += (size_t)blockIdx.z * (size_t)M * (size_t)ldc;

    float acc[TM][TN];
#pragma unroll
    for (int i = 0; i < TM; i++)
#pragma unroll
        for (int j = 0; j < TN; j++) acc[i][j] = 0.f;

    for (int kt = 0; kt < kChunk; kt += BK) {
        const int kk = kBase + kt;
        // load A tile (transposed into smem)
        for (int idx = tid; idx < BM * KV; idx += NT) {
            int m  = idx / KV;
            int kv = (idx % KV) * 4;
            const float4 v = *(const float4*)&A[(size_t)(m0 + m) * lda + kk + kv];
            As[kv + 0][m] = v.x; As[kv + 1][m] = v.y;
            As[kv + 2][m] = v.z; As[kv + 3][m] = v.w;
        }
        // load W tile (transposed into smem)
        for (int idx = tid; idx < BN * KV; idx += NT) {
            int n  = idx / KV;
            int kv = (idx % KV) * 4;
            const float4 v = *(const float4*)&W[(size_t)(n0 + n) * K + kk + kv];
            Bs[kv + 0][n] = v.x; Bs[kv + 1][n] = v.y;
            Bs[kv + 2][n] = v.z; Bs[kv + 3][n] = v.w;
        }
        __syncthreads();
#pragma unroll
        for (int k = 0; k < BK; k++) {
            float a[TM], b[TN];
#pragma unroll
            for (int i = 0; i < TM; i++) a[i] = As[k][ty * TM + i];
#pragma unroll
            for (int j = 0; j < TN; j++) b[j] = Bs[k][tx * TN + j];
#pragma unroll
            for (int i = 0; i < TM; i++)
#pragma unroll
                for (int j = 0; j < TN; j++) acc[i][j] = fmaf(a[i], b[j], acc[i][j]);
        }
        __syncthreads();
    }

#pragma unroll
    for (int i = 0; i < TM; i++) {
        int m = m0 + ty * TM + i;
#pragma unroll
        for (int j = 0; j < TN; j++) {
            int n = n0 + tx * TN + j;
            float v = acc[i][j];
            if (EPI == 1) {
                v += bias[n];
                // softplus: max(x,0) + log1p(exp(-|x|))
                v = fmaxf(v, 0.f) + log1pf(expf(-fabsf(v)));
            }
            C[(size_t)m * ldc + n] = v;
        }
    }
}

// ---------------- Reduce split-K partials for x_proj ----------------
__global__ void reduce_xdbl_kernel()
{
    int idx = blockIdx.x * blockDim.x + threadIdx.x;   // over MROWS*96
    if (idx >= MROWS * XDBL_N) return;
    float s = 0.f;
#pragma unroll
    for (int z = 0; z < SPLITK_XPROJ; z++)
        s += g_xdbl_part[(size_t)z * MROWS * XDBL_N + idx];
    g_xdbl[idx] = s;
}

// ---------------- Depthwise causal conv (width 4) + SiLU ----------------
__global__ void conv_silu_kernel(const float* __restrict__ xz,   // [B][L][2*DI], first half is xa
                                 const float* __restrict__ cw,   // [DI][4]
                                 const float* __restrict__ cb,   // [DI]
                                 float* __restrict__ xa_out)     // [B][L][DI]
{
    int idx = blockIdx.x * blockDim.x + threadIdx.x;   // over B*L*DI
    if (idx >= MROWS * D_INNER) return;
    int d = idx % D_INNER;
    int l = (idx / D_INNER) % SEQ;
    int b = idx / (D_INNER * SEQ);
    float s = cb[d];
#pragma unroll
    for (int j = 0; j < 4; j++) {
        int ls = l + j - 3;
        if (ls >= 0)
            s += cw[d * 4 + j] * xz[((size_t)(b * SEQ + ls)) * (2 * D_INNER) + d];
    }
    float sig = 1.f / (1.f + expf(-s));
    xa_out[idx] = s * sig;
}

// ---------------- Selective scan + C-contraction + D-skip + z-gating ----------------
// Thread layout: block = 256 threads = 16 d-channels x 16 states, per (b, d-group).
// Each thread owns one (d, n) recurrence in a register; 16-lane shfl reduce for sum_n h*C.
__global__ void scan_kernel(const float* __restrict__ xz,     // [B][L][2*DI] (z at +DI)
                            const float* __restrict__ xa,     // [B][L][DI]
                            const float* __restrict__ xdbl,   // [B][L][96] (B at 64, C at 80)
                            const float* __restrict__ dt,     // [B][L][DI]
                            const float* __restrict__ A_log,  // [DI][16]
                            const float* __restrict__ Dp,     // [DI]
                            float* __restrict__ y)            // [B][L][DI]
{
    const int grp = blockIdx.x;                 // B * (DI/16) = 256 blocks
    const int b   = grp / (D_INNER / 16);
    const int d0  = (grp % (D_INNER / 16)) * 16;
    const int tid = threadIdx.x;
    const int n   = tid & 15;
    const int dl  = tid >> 4;                   // 0..15
    const int d   = d0 + dl;

    const float aln = -expf(A_log[d * D_STATE + n]) * 1.44269504088896340736f; // A * log2(e)
    const float Dv  = Dp[d];

    __shared__ float dt_s[32][16], xa_s[32][16], z_s[32][16], Bm_s[32][16], Cm_s[32][16];

    float h = 0.f;
    for (int l0 = 0; l0 < SEQ; l0 += 32) {
        for (int idx = tid; idx < 32 * 16; idx += 256) {
            int l = idx >> 4, q = idx & 15;
            size_t row = (size_t)(b * SEQ + l0 + l);
            dt_s[l][q] = dt[row * D_INNER + d0 + q];
            xa_s[l][q] = xa[row * D_INNER + d0 + q];
            z_s[l][q]  = xz[row * (2 * D_INNER) + D_INNER + d0 + q];
            Bm_s[l][q] = xdbl[row * XDBL_N + DT_RANK + q];
            Cm_s[l][q] = xdbl[row * XDBL_N + DT_RANK + D_STATE + q];
        }
        __syncthreads();
#pragma unroll 4
        for (int l = 0; l < 32; l++) {
            float dtv = dt_s[l][dl];
            float xav = xa_s[l][dl];
            float da  = exp2f(dtv * aln);                 // exp(dt*A)
            float bx  = dtv * Bm_s[l][n] * xav;           // dt * B * x
            h = fmaf(da, h, bx);
            float contrib = h * Cm_s[l][n];
#pragma unroll
            for (int off = 8; off; off >>= 1)
                contrib += __shfl_xor_sync(0xFFFFFFFFu, contrib, off);
            if (n == 0) {
                float zv   = z_s[l][dl];
                float gate = zv / (1.f + expf(-zv));      // silu(z)
                y[((size_t)(b * SEQ + l0 + l)) * D_INNER + d] =
                    (contrib + xav * Dv) * gate;
            }
        }
        __syncthreads();
    }
}

// ---------------- Host launch ----------------
extern "C" void kernel_launch(void* const* d_in, const int* in_sizes, int n_in,
                              void* d_out, int out_size)
{
    const float* condition = (const float*)d_in[0];   // (2,1)
    const float* pe        = (const float*)d_in[1];   // (1,512,1024)
    const float* to_cond_w = (const float*)d_in[2];   // (1024,1)
    const float* to_cond_b = (const float*)d_in[3];   // (1024,)
    const float* in_proj_w = (const float*)d_in[4];   // (4,4096,1024)
    const float* conv_w    = (const float*)d_in[5];   // (4,2048,4)
    const float* conv_b    = (const float*)d_in[6];   // (4,2048)
    const float* x_proj_w  = (const float*)d_in[7];   // (4,96,2048)
    const float* dt_proj_w = (const float*)d_in[8];   // (4,2048,64)
    const float* dt_proj_b = (const float*)d_in[9];   // (4,2048)
    const float* A_log     = (const float*)d_in[10];  // (4,2048,16)
    const float* D_skip    = (const float*)d_in[11];  // (4,2048)
    const float* out_w     = (const float*)d_in[12];  // (4,1024,2048)
    float* out = (float*)d_out;                       // (2,512,1024)

    float *px0, *px1, *pxz, *pxa, *pxdbl, *pxdbl_part, *pdt, *py;
    cudaGetSymbolAddress((void**)&px0, g_x0);
    cudaGetSymbolAddress((void**)&px1, g_x1);
    cudaGetSymbolAddress((void**)&pxz, g_xz);
    cudaGetSymbolAddress((void**)&pxa, g_xa);
    cudaGetSymbolAddress((void**)&pxdbl, g_xdbl);
    cudaGetSymbolAddress((void**)&pxdbl_part, g_xdbl_part);
    cudaGetSymbolAddress((void**)&pdt, g_dt);
    cudaGetSymbolAddress((void**)&py, g_y);

    // prologue
    prologue_kernel<<<(MROWS * D_MODEL + 255) / 256, 256>>>(condition, pe, to_cond_w, to_cond_b, px0);

    const float* xin = px0;
    for (int i = 0; i < N_LAYERS; i++) {
        const float* wi  = in_proj_w + (size_t)i * 2 * D_INNER * D_MODEL;
        const float* cwi = conv_w    + (size_t)i * D_INNER * 4;
        const float* cbi = conv_b    + (size_t)i * D_INNER;
        const float* xpi = x_proj_w  + (size_t)i * XDBL_N * D_INNER;
        const float* dpi = dt_proj_w + (size_t)i * D_INNER * DT_RANK;
        const float* dbi = dt_proj_b + (size_t)i * D_INNER;
        const float* ali = A_log     + (size_t)i * D_INNER * D_STATE;
        const float* di  = D_skip    + (size_t)i * D_INNER;
        const float* owi = out_w     + (size_t)i * D_MODEL * D_INNER;
        float* xout = (i == N_LAYERS - 1) ? out : ((i & 1) ? px0 : px1);

        // 1) in_proj: [1024,1024] x [4096,1024]^T -> xz
        gemm_nt<128, 128, 16, 8, 8, 0>
            <<<dim3(2 * D_INNER / 128, MROWS / 128, 1), 256>>>(
                xin, wi, nullptr, pxz, MROWS, 2 * D_INNER, D_MODEL, D_MODEL, 2 * D_INNER);

        // 2) depthwise causal conv + silu
        conv_silu_kernel<<<(MROWS * D_INNER + 255) / 256, 256>>>(pxz, cwi, cbi, pxa);

        // 3) x_proj (split-K partials): [1024,2048] x [96,2048]^T
        gemm_nt<64, 96, 16, 4, 6, 0>
            <<<dim3(1, MROWS / 64, SPLITK_XPROJ), 256>>>(
                pxa, xpi, nullptr, pxdbl_part, MROWS, XDBL_N, D_INNER, D_INNER, XDBL_N);
        reduce_xdbl_kernel<<<(MROWS * XDBL_N + 255) / 256, 256>>>();

        // 4) dt_proj + bias + softplus: A = x_dbl[:, :64] (lda=96), K=64
        gemm_nt<64, 64, 16, 4, 4, 1>
            <<<dim3(D_INNER / 64, MROWS / 64, 1), 256>>>(
                pxdbl, dpi, dbi, pdt, MROWS, D_INNER, DT_RANK, XDBL_N, D_INNER);

        // 5) selective scan + gating
        scan_kernel<<<BATCH * (D_INNER / 16), 256>>>(pxz, pxa, pxdbl, pdt, ali, di, py);

        // 6) out_proj: [1024,2048] x [1024,2048]^T -> next x
        gemm_nt<64, 64, 16, 4, 4, 0>
            <<<dim3(D_MODEL / 64, MROWS / 64, 1), 256>>>(
                py, owi, nullptr, xout, MROWS, D_MODEL, D_INNER, D_INNER, D_MODEL);

        xin = xout;
    }
}

// round 4
// speedup vs baseline: 1.6651x; 1.6651x over previous
#include <cuda_runtime.h>
#include <cuda_bf16.h>
#include <math.h>
#include <stdint.h>

// ---------------- Problem constants ----------------
#define BATCH    2
#define SEQ      512
#define D_MODEL  1024
#define D_INNER  2048
#define D_STATE  16
#define DT_RANK  64
#define N_LAYERS 4
#define MROWS    (BATCH * SEQ)           // 1024
#define XDBL_N   (DT_RANK + 2 * D_STATE) // 96
#define SPLITK_XPROJ 32

// ---------------- Scratch (__device__ globals; no allocation allowed) ----------------
__device__ float g_x0[MROWS * D_MODEL];
__device__ float g_x1[MROWS * D_MODEL];
__device__ float g_xz[MROWS * 2 * D_INNER];
__device__ float g_xa[MROWS * D_INNER];
__device__ float g_xdbl[MROWS * XDBL_N];
__device__ float g_xdbl_part[SPLITK_XPROJ * MROWS * XDBL_N];
__device__ float g_dt[MROWS * D_INNER];
__device__ float g_y[MROWS * D_INNER];

// ---------------- warp-mma helpers ----------------
__device__ __forceinline__ uint32_t smem_u32(const void* p) {
    uint32_t a;
    asm("{ .reg .u64 t; cvta.to.shared.u64 t, %1; cvt.u32.u64 %0, t; }" : "=r"(a) : "l"(p));
    return a;
}
__device__ __forceinline__ void ldsm4(uint32_t* r, uint32_t addr) {
    asm volatile("ldmatrix.sync.aligned.m8n8.x4.shared.b16 {%0,%1,%2,%3}, [%4];"
                 : "=r"(r[0]), "=r"(r[1]), "=r"(r[2]), "=r"(r[3]) : "r"(addr));
}
__device__ __forceinline__ void mma16816(float* c, const uint32_t* a, uint32_t b0, uint32_t b1) {
    asm volatile("mma.sync.aligned.m16n8k16.row.col.f32.bf16.bf16.f32 "
                 "{%0,%1,%2,%3}, {%4,%5,%6,%7}, {%8,%9}, {%0,%1,%2,%3};"
                 : "+f"(c[0]), "+f"(c[1]), "+f"(c[2]), "+f"(c[3])
                 : "r"(a[0]), "r"(a[1]), "r"(a[2]), "r"(a[3]), "r"(b0), "r"(b1));
}
__device__ __forceinline__ uint32_t bf16_hi(float v) {
    __nv_bfloat16 h = __float2bfloat16(v);
    return (uint32_t)*(unsigned short*)&h;
}
__device__ __forceinline__ void split2(float v0, float v1, uint32_t& hi, uint32_t& lo) {
    __nv_bfloat16 h0 = __float2bfloat16(v0);
    __nv_bfloat16 h1 = __float2bfloat16(v1);
    __nv_bfloat16 l0 = __float2bfloat16(v0 - __bfloat162float(h0));
    __nv_bfloat16 l1 = __float2bfloat16(v1 - __bfloat162float(h1));
    hi = (uint32_t)*(unsigned short*)&h0 | ((uint32_t)*(unsigned short*)&h1 << 16);
    lo = (uint32_t)*(unsigned short*)&l0 | ((uint32_t)*(unsigned short*)&l1 << 16);
}

// ============================================================
// bf16-split NT GEMM via mma.sync:  C[m,n] = sum_k A[m,k] * W[n,k]
// BM=128, BK=32; 3-term hi/lo split; double-buffered smem (80B rows).
// ============================================================
template<int BN>
__global__ void __launch_bounds__(256, 1)
gemm_mma(const float* __restrict__ A, const float* __restrict__ W,
         float* __restrict__ C, int K, int lda, int ldw, int ldc)
{
    constexpr int BM = 128, BK = 32;
    constexpr int WN = BN / 4;          // warp n extent (32 or 16)
    constexpr int NF16 = WN / 16;       // 2 or 1
    constexpr int A_CH_T = (BM * BK / 8) / 256;  // chunks (8 floats) per thread = 2
    constexpr int B_CH_T = (BN * BK / 8) / 256;  // 2 or 1
    constexpr int ROWB = 80;            // padded 64B row -> conflict-free ldmatrix
    constexpr int A_SZ = BM * ROWB;     // 10240
    constexpr int B_SZ = BN * ROWB;
    constexpr int AH = 0, AL = A_SZ, WH = 2 * A_SZ, WL = 2 * A_SZ + B_SZ;
    constexpr int STAGE = 2 * A_SZ + 2 * B_SZ;

    extern __shared__ char smem[];
    const uint32_t sbase = smem_u32(smem);
    const int tid = threadIdx.x;
    const int lane = tid & 31, wid = tid >> 5;
    const int wm = wid & 1, wn = wid >> 1;
    const int m0 = blockIdx.y * BM, n0 = blockIdx.x * BN;

    float acc[4][2 * NF16][4];
#pragma unroll
    for (int i = 0; i < 4; i++)
#pragma unroll
        for (int j = 0; j < 2 * NF16; j++)
#pragma unroll
            for (int e = 0; e < 4; e++) acc[i][j][e] = 0.f;

    // ldmatrix lane base offsets
    const uint32_t a_off = (uint32_t)((wm * 64 + (lane & 15)) * ROWB + (lane >> 4) * 16);
    const uint32_t b_off = (uint32_t)((wn * WN + (lane & 7) + ((lane >> 4) & 1) * 8) * ROWB
                                      + ((lane >> 3) & 1) * 16);

    float4 sa[2 * A_CH_T];
    float4 sb[2 * B_CH_T];

    auto LOAD = [&](int kk) {
#pragma unroll
        for (int j = 0; j < A_CH_T; j++) {
            int ch = tid + j * 256;
            int r = ch >> 2, c = ch & 3;
            const float* p = &A[(size_t)(m0 + r) * lda + kk + c * 8];
            sa[2 * j]     = *(const float4*)(p);
            sa[2 * j + 1] = *(const float4*)(p + 4);
        }
#pragma unroll
        for (int j = 0; j < B_CH_T; j++) {
            int ch = tid + j * 256;
            int r = ch >> 2, c = ch & 3;
            const float* p = &W[(size_t)(n0 + r) * ldw + kk + c * 8];
            sb[2 * j]     = *(const float4*)(p);
            sb[2 * j + 1] = *(const float4*)(p + 4);
        }
    };

    auto STORE = [&](int buf) {
        char* s = smem + buf * STAGE;
#pragma unroll
        for (int j = 0; j < A_CH_T; j++) {
            int ch = tid + j * 256;
            int r = ch >> 2, c = ch & 3;
            uint4 hi, lo;
            split2(sa[2*j].x,   sa[2*j].y,   hi.x, lo.x);
            split2(sa[2*j].z,   sa[2*j].w,   hi.y, lo.y);
            split2(sa[2*j+1].x, sa[2*j+1].y, hi.z, lo.z);
            split2(sa[2*j+1].z, sa[2*j+1].w, hi.w, lo.w);
            *(uint4*)(s + AH + r * ROWB + c * 16) = hi;
            *(uint4*)(s + AL + r * ROWB + c * 16) = lo;
        }
#pragma unroll
        for (int j = 0; j < B_CH_T; j++) {
            int ch = tid + j * 256;
            int r = ch >> 2, c = ch & 3;
            uint4 hi, lo;
            split2(sb[2*j].x,   sb[2*j].y,   hi.x, lo.x);
            split2(sb[2*j].z,   sb[2*j].w,   hi.y, lo.y);
            split2(sb[2*j+1].x, sb[2*j+1].y, hi.z, lo.z);
            split2(sb[2*j+1].z, sb[2*j+1].w, hi.w, lo.w);
            *(uint4*)(s + WH + r * ROWB + c * 16) = hi;
            *(uint4*)(s + WL + r * ROWB + c * 16) = lo;
        }
    };

    auto MMA = [&](int buf) {
        const uint32_t sb32 = sbase + (uint32_t)(buf * STAGE);
#pragma unroll
        for (int ks = 0; ks < 2; ks++) {
            uint32_t ah[4][4], al[4][4], bh[NF16][4], bl[NF16][4];
#pragma unroll
            for (int mf = 0; mf < 4; mf++) {
                uint32_t o = sb32 + a_off + (uint32_t)(mf * 16 * ROWB + ks * 32);
                ldsm4(ah[mf], o + AH);
                ldsm4(al[mf], o + AL);
            }
#pragma unroll
            for (int g = 0; g < NF16; g++) {
                uint32_t o = sb32 + b_off + (uint32_t)(g * 16 * ROWB + ks * 32);
                ldsm4(bh[g], o + WH);
                ldsm4(bl[g], o + WL);
            }
#pragma unroll
            for (int mf = 0; mf < 4; mf++)
#pragma unroll
                for (int g = 0; g < NF16; g++)
#pragma unroll
                    for (int h = 0; h < 2; h++) {
                        float* c = acc[mf][2 * g + h];
                        mma16816(c, ah[mf], bh[g][2 * h], bh[g][2 * h + 1]);
                        mma16816(c, ah[mf], bl[g][2 * h], bl[g][2 * h + 1]);
                        mma16816(c, al[mf], bh[g][2 * h], bh[g][2 * h + 1]);
                    }
        }
    };

    const int nt = K / BK;
    LOAD(0);
    for (int kt = 0; kt < nt; kt++) {
        STORE(kt & 1);
        __syncthreads();
        if (kt + 1 < nt) LOAD((kt + 1) * BK);
        MMA(kt & 1);
    }

    // epilogue
    const int gid = lane >> 2, tig = lane & 3;
#pragma unroll
    for (int mf = 0; mf < 4; mf++) {
        int row = m0 + wm * 64 + mf * 16 + gid;
#pragma unroll
        for (int gn = 0; gn < 2 * NF16; gn++) {
            int col = n0 + wn * WN + gn * 8 + 2 * tig;
            float2 v0 = make_float2(acc[mf][gn][0], acc[mf][gn][1]);
            float2 v1 = make_float2(acc[mf][gn][2], acc[mf][gn][3]);
            *(float2*)&C[(size_t)row * ldc + col]       = v0;
            *(float2*)&C[(size_t)(row + 8) * ldc + col] = v1;
        }
    }
}

// ---------------- Prologue: x = pe + cond ----------------
__global__ void prologue_kernel(const float* __restrict__ condition,
                                const float* __restrict__ pe,
                                const float* __restrict__ to_cond_w,
                                const float* __restrict__ to_cond_b,
                                float* __restrict__ x)
{
    int idx = blockIdx.x * blockDim.x + threadIdx.x;
    if (idx >= MROWS * D_MODEL) return;
    int d = idx % D_MODEL;
    int l = (idx / D_MODEL) % SEQ;
    int b = idx / (D_MODEL * SEQ);
    float cond = condition[b] * to_cond_w[d] + to_cond_b[d];
    x[idx] = pe[l * D_MODEL + d] + cond;
}

// ---------------- SIMT NT GEMM (small matmuls) ----------------
template<int BM, int BN, int BK, int TM, int TN, int EPI>
__global__ void gemm_nt(const float* __restrict__ A,
                        const float* __restrict__ W,
                        const float* __restrict__ bias,
                        float* __restrict__ C,
                        int M, int N, int K, int lda, int ldc)
{
    constexpr int TX = BN / TN;
    constexpr int TY = BM / TM;
    constexpr int NT = TX * TY;
    constexpr int KV = BK / 4;

    __shared__ float As[BK][BM + 4];
    __shared__ float Bs[BK][BN + 4];

    const int tid = threadIdx.x;
    const int tx  = tid % TX;
    const int ty  = tid / TX;
    const int n0  = blockIdx.x * BN;
    const int m0  = blockIdx.y * BM;

    const int kChunk = K / gridDim.z;
    const int kBase  = blockIdx.z * kChunk;
    C += (size_t)blockIdx.z * (size_t)M * (size_t)ldc;

    float acc[TM][TN];
#pragma unroll
    for (int i = 0; i < TM; i++)
#pragma unroll
        for (int j = 0; j < TN; j++) acc[i][j] = 0.f;

    for (int kt = 0; kt < kChunk; kt += BK) {
        const int kk = kBase + kt;
        for (int idx = tid; idx < BM * KV; idx += NT) {
            int m  = idx / KV;
            int kv = (idx % KV) * 4;
            const float4 v = *(const float4*)&A[(size_t)(m0 + m) * lda + kk + kv];
            As[kv + 0][m] = v.x; As[kv + 1][m] = v.y;
            As[kv + 2][m] = v.z; As[kv + 3][m] = v.w;
        }
        for (int idx = tid; idx < BN * KV; idx += NT) {
            int n  = idx / KV;
            int kv = (idx % KV) * 4;
            const float4 v = *(const float4*)&W[(size_t)(n0 + n) * K + kk + kv];
            Bs[kv + 0][n] = v.x; Bs[kv + 1][n] = v.y;
            Bs[kv + 2][n] = v.z; Bs[kv + 3][n] = v.w;
        }
        __syncthreads();
#pragma unroll
        for (int k = 0; k < BK; k++) {
            float a[TM], b[TN];
#pragma unroll
            for (int i = 0; i < TM; i++) a[i] = As[k][ty * TM + i];
#pragma unroll
            for (int j = 0; j < TN; j++) b[j] = Bs[k][tx * TN + j];
#pragma unroll
            for (int i = 0; i < TM; i++)
#pragma unroll
                for (int j = 0; j < TN; j++) acc[i][j] = fmaf(a[i], b[j], acc[i][j]);
        }
        __syncthreads();
    }

#pragma unroll
    for (int i = 0; i < TM; i++) {
        int m = m0 + ty * TM + i;
#pragma unroll
        for (int j = 0; j < TN; j++) {
            int n = n0 + tx * TN + j;
            float v = acc[i][j];
            if (EPI == 1) {
                v += bias[n];
                v = fmaxf(v, 0.f) + log1pf(expf(-fabsf(v)));
            }
            C[(size_t)m * ldc + n] = v;
        }
    }
}

// ---------------- Reduce split-K partials for x_proj ----------------
__global__ void reduce_xdbl_kernel()
{
    int idx = blockIdx.x * blockDim.x + threadIdx.x;
    if (idx >= MROWS * XDBL_N) return;
    float s = 0.f;
#pragma unroll
    for (int z = 0; z < SPLITK_XPROJ; z++)
        s += g_xdbl_part[(size_t)z * MROWS * XDBL_N + idx];
    g_xdbl[idx] = s;
}

// ---------------- Depthwise causal conv (width 4) + SiLU ----------------
__global__ void conv_silu_kernel(const float* __restrict__ xz,
                                 const float* __restrict__ cw,
                                 const float* __restrict__ cb,
                                 float* __restrict__ xa_out)
{
    int idx = blockIdx.x * blockDim.x + threadIdx.x;
    if (idx >= MROWS * D_INNER) return;
    int d = idx % D_INNER;
    int l = (idx / D_INNER) % SEQ;
    int b = idx / (D_INNER * SEQ);
    float s = cb[d];
#pragma unroll
    for (int j = 0; j < 4; j++) {
        int ls = l + j - 3;
        if (ls >= 0)
            s += cw[d * 4 + j] * xz[((size_t)(b * SEQ + ls)) * (2 * D_INNER) + d];
    }
    float sig = 1.f / (1.f + expf(-s));
    xa_out[idx] = s * sig;
}

// ---------------- Selective scan + gating ----------------
__global__ void scan_kernel(const float* __restrict__ xz,
                            const float* __restrict__ xa,
                            const float* __restrict__ xdbl,
                            const float* __restrict__ dt,
                            const float* __restrict__ A_log,
                            const float* __restrict__ Dp,
                            float* __restrict__ y)
{
    const int grp = blockIdx.x;
    const int b   = grp / (D_INNER / 16);
    const int d0  = (grp % (D_INNER / 16)) * 16;
    const int tid = threadIdx.x;
    const int n   = tid & 15;
    const int dl  = tid >> 4;
    const int d   = d0 + dl;

    const float aln = -expf(A_log[d * D_STATE + n]) * 1.44269504088896340736f;
    const float Dv  = Dp[d];

    __shared__ float dt_s[32][16], xa_s[32][16], z_s[32][16], Bm_s[32][16], Cm_s[32][16];

    float h = 0.f;
    for (int l0 = 0; l0 < SEQ; l0 += 32) {
        for (int idx = tid; idx < 32 * 16; idx += 256) {
            int l = idx >> 4, q = idx & 15;
            size_t row = (size_t)(b * SEQ + l0 + l);
            dt_s[l][q] = dt[row * D_INNER + d0 + q];
            xa_s[l][q] = xa[row * D_INNER + d0 + q];
            z_s[l][q]  = xz[row * (2 * D_INNER) + D_INNER + d0 + q];
            Bm_s[l][q] = xdbl[row * XDBL_N + DT_RANK + q];
            Cm_s[l][q] = xdbl[row * XDBL_N + DT_RANK + D_STATE + q];
        }
        __syncthreads();
#pragma unroll 4
        for (int l = 0; l < 32; l++) {
            float dtv = dt_s[l][dl];
            float xav = xa_s[l][dl];
            float da  = exp2f(dtv * aln);
            float bx  = dtv * Bm_s[l][n] * xav;
            h = fmaf(da, h, bx);
            float contrib = h * Cm_s[l][n];
#pragma unroll
            for (int off = 8; off; off >>= 1)
                contrib += __shfl_xor_sync(0xFFFFFFFFu, contrib, off);
            if (n == 0) {
                float zv   = z_s[l][dl];
                float gate = zv / (1.f + expf(-zv));
                y[((size_t)(b * SEQ + l0 + l)) * D_INNER + d] =
                    (contrib + xav * Dv) * gate;
            }
        }
        __syncthreads();
    }
}

// ---------------- Host launch ----------------
extern "C" void kernel_launch(void* const* d_in, const int* in_sizes, int n_in,
                              void* d_out, int out_size)
{
    const float* condition = (const float*)d_in[0];
    const float* pe        = (const float*)d_in[1];
    const float* to_cond_w = (const float*)d_in[2];
    const float* to_cond_b = (const float*)d_in[3];
    const float* in_proj_w = (const float*)d_in[4];
    const float* conv_w    = (const float*)d_in[5];
    const float* conv_b    = (const float*)d_in[6];
    const float* x_proj_w  = (const float*)d_in[7];
    const float* dt_proj_w = (const float*)d_in[8];
    const float* dt_proj_b = (const float*)d_in[9];
    const float* A_log     = (const float*)d_in[10];
    const float* D_skip    = (const float*)d_in[11];
    const float* out_w     = (const float*)d_in[12];
    float* out = (float*)d_out;

    float *px0, *px1, *pxz, *pxa, *pxdbl, *pxdbl_part, *pdt, *py;
    cudaGetSymbolAddress((void**)&px0, g_x0);
    cudaGetSymbolAddress((void**)&px1, g_x1);
    cudaGetSymbolAddress((void**)&pxz, g_xz);
    cudaGetSymbolAddress((void**)&pxa, g_xa);
    cudaGetSymbolAddress((void**)&pxdbl, g_xdbl);
    cudaGetSymbolAddress((void**)&pxdbl_part, g_xdbl_part);
    cudaGetSymbolAddress((void**)&pdt, g_dt);
    cudaGetSymbolAddress((void**)&py, g_y);

    // dynamic smem: BN=128 -> 2*(2*10240 + 2*10240) = 81920; BN=64 -> 61440
    const int SMEM_128 = 81920;
    const int SMEM_64  = 61440;
    cudaFuncSetAttribute(gemm_mma<128>, cudaFuncAttributeMaxDynamicSharedMemorySize, SMEM_128);
    cudaFuncSetAttribute(gemm_mma<64>,  cudaFuncAttributeMaxDynamicSharedMemorySize, SMEM_64);

    prologue_kernel<<<(MROWS * D_MODEL + 255) / 256, 256>>>(condition, pe, to_cond_w, to_cond_b, px0);

    const float* xin = px0;
    for (int i = 0; i < N_LAYERS; i++) {
        const float* wi  = in_proj_w + (size_t)i * 2 * D_INNER * D_MODEL;
        const float* cwi = conv_w    + (size_t)i * D_INNER * 4;
        const float* cbi = conv_b    + (size_t)i * D_INNER;
        const float* xpi = x_proj_w  + (size_t)i * XDBL_N * D_INNER;
        const float* dpi = dt_proj_w + (size_t)i * D_INNER * DT_RANK;
        const float* dbi = dt_proj_b + (size_t)i * D_INNER;
        const float* ali = A_log     + (size_t)i * D_INNER * D_STATE;
        const float* di  = D_skip    + (size_t)i * D_INNER;
        const float* owi = out_w     + (size_t)i * D_MODEL * D_INNER;
        float* xout = (i == N_LAYERS - 1) ? out : ((i & 1) ? px0 : px1);

        // 1) in_proj (mma): [1024,1024] x [4096,1024]^T
        gemm_mma<128><<<dim3(2 * D_INNER / 128, MROWS / 128), 256, SMEM_128>>>(
            xin, wi, pxz, D_MODEL, D_MODEL, D_MODEL, 2 * D_INNER);

        // 2) depthwise causal conv + silu
        conv_silu_kernel<<<(MROWS * D_INNER + 255) / 256, 256>>>(pxz, cwi, cbi, pxa);

        // 3) x_proj (SIMT split-K 32)
        gemm_nt<64, 96, 16, 4, 6, 0>
            <<<dim3(1, MROWS / 64, SPLITK_XPROJ), 256>>>(
                pxa, xpi, nullptr, pxdbl_part, MROWS, XDBL_N, D_INNER, D_INNER, XDBL_N);
        reduce_xdbl_kernel<<<(MROWS * XDBL_N + 255) / 256, 256>>>();

        // 4) dt_proj + bias + softplus
        gemm_nt<64, 64, 16, 4, 4, 1>
            <<<dim3(D_INNER / 64, MROWS / 64, 1), 256>>>(
                pxdbl, dpi, dbi, pdt, MROWS, D_INNER, DT_RANK, XDBL_N, D_INNER);

        // 5) selective scan + gating
        scan_kernel<<<BATCH * (D_INNER / 16), 256>>>(pxz, pxa, pxdbl, pdt, ali, di, py);

        // 6) out_proj (mma): [1024,2048] x [1024,2048]^T
        gemm_mma<64><<<dim3(D_MODEL / 64, MROWS / 128), 256, SMEM_64>>>(
            py, owi, xout, D_INNER, D_INNER, D_INNER, D_MODEL);

        xin = xout;
    }
}

// round 5
// speedup vs baseline: 1.7553x; 1.0542x over previous
#include <cuda_runtime.h>
#include <cuda_bf16.h>
#include <math.h>
#include <stdint.h>

// ---------------- Problem constants ----------------
#define BATCH    2
#define SEQ      512
#define D_MODEL  1024
#define D_INNER  2048
#define D_STATE  16
#define DT_RANK  64
#define N_LAYERS 4
#define MROWS    (BATCH * SEQ)           // 1024
#define XDBL_N   (DT_RANK + 2 * D_STATE) // 96
#define SPLITK_XPROJ 32

// ---------------- Scratch (__device__ globals; no allocation allowed) ----------------
__device__ float g_xz[MROWS * 2 * D_INNER];
__device__ float g_xa[MROWS * D_INNER];
__device__ float g_xdbl[MROWS * XDBL_N];
__device__ float g_xdbl_part[SPLITK_XPROJ * MROWS * XDBL_N];
__device__ float g_dt[MROWS * D_INNER];

// bf16 hi/lo activations
__device__ __nv_bfloat16 g_xh[MROWS * D_MODEL];
__device__ __nv_bfloat16 g_xl[MROWS * D_MODEL];
__device__ __nv_bfloat16 g_yh[MROWS * D_INNER];
__device__ __nv_bfloat16 g_yl[MROWS * D_INNER];
// bf16 hi/lo prepacked weights
__device__ __nv_bfloat16 g_wih[N_LAYERS * 2 * D_INNER * D_MODEL];
__device__ __nv_bfloat16 g_wil[N_LAYERS * 2 * D_INNER * D_MODEL];
__device__ __nv_bfloat16 g_woh[N_LAYERS * D_MODEL * D_INNER];
__device__ __nv_bfloat16 g_wol[N_LAYERS * D_MODEL * D_INNER];

// ---------------- helpers ----------------
__device__ __forceinline__ uint32_t smem_u32(const void* p) {
    uint32_t a;
    asm("{ .reg .u64 t; cvta.to.shared.u64 t, %1; cvt.u32.u64 %0, t; }" : "=r"(a) : "l"(p));
    return a;
}
__device__ __forceinline__ void ldsm4(uint32_t* r, uint32_t addr) {
    asm volatile("ldmatrix.sync.aligned.m8n8.x4.shared.b16 {%0,%1,%2,%3}, [%4];"
                 : "=r"(r[0]), "=r"(r[1]), "=r"(r[2]), "=r"(r[3]) : "r"(addr));
}
__device__ __forceinline__ void mma16816(float* c, const uint32_t* a, uint32_t b0, uint32_t b1) {
    asm volatile("mma.sync.aligned.m16n8k16.row.col.f32.bf16.bf16.f32 "
                 "{%0,%1,%2,%3}, {%4,%5,%6,%7}, {%8,%9}, {%0,%1,%2,%3};"
                 : "+f"(c[0]), "+f"(c[1]), "+f"(c[2]), "+f"(c[3])
                 : "r"(a[0]), "r"(a[1]), "r"(a[2]), "r"(a[3]), "r"(b0), "r"(b1));
}
__device__ __forceinline__ void cp16(uint32_t dst, const void* src) {
    asm volatile("cp.async.cg.shared.global [%0], [%1], 16;" :: "r"(dst), "l"(src));
}
__device__ __forceinline__ void split2(float v0, float v1, uint32_t& hi, uint32_t& lo) {
    __nv_bfloat16 h0 = __float2bfloat16(v0);
    __nv_bfloat16 h1 = __float2bfloat16(v1);
    __nv_bfloat16 l0 = __float2bfloat16(v0 - __bfloat162float(h0));
    __nv_bfloat16 l1 = __float2bfloat16(v1 - __bfloat162float(h1));
    hi = (uint32_t)*(unsigned short*)&h0 | ((uint32_t)*(unsigned short*)&h1 << 16);
    lo = (uint32_t)*(unsigned short*)&l0 | ((uint32_t)*(unsigned short*)&l1 << 16);
}

// ---------------- Weight prepack: fp32 -> bf16 hi/lo ----------------
__global__ void prepack_kernel(const float* __restrict__ src,
                               __nv_bfloat16* __restrict__ hi,
                               __nv_bfloat16* __restrict__ lo, int n)
{
    int i = (blockIdx.x * blockDim.x + threadIdx.x) * 4;
    if (i >= n) return;
    float4 f = *(const float4*)(src + i);
    uint2 hv, lv;
    split2(f.x, f.y, hv.x, lv.x);
    split2(f.z, f.w, hv.y, lv.y);
    *(uint2*)((unsigned short*)hi + i) = hv;
    *(uint2*)((unsigned short*)lo + i) = lv;
}

// ============================================================
// bf16-split NT GEMM via mma.sync + cp.async 3-stage pipeline.
// C[m,n] = sum_k A[m,k]*W[n,k], inputs prepacked bf16 hi/lo.
// BM=128, BK=32. EMIT: 0 = fp32 C, 1 = bf16 hi/lo C.
// ============================================================
template<int BN, int EMIT>
__global__ void __launch_bounds__(256, 1)
gemm_bf16(const __nv_bfloat16* __restrict__ Ah, const __nv_bfloat16* __restrict__ Al,
          const __nv_bfloat16* __restrict__ Wh, const __nv_bfloat16* __restrict__ Wl,
          float* __restrict__ C, __nv_bfloat16* __restrict__ Ch, __nv_bfloat16* __restrict__ Cl,
          int K, int ldc)
{
    constexpr int BM = 128, BK = 32, ROWB = 80, NSTG = 3;
    constexpr int WN = BN / 4;
    constexpr int NF16 = WN / 16;               // 2 (BN=128) or 1 (BN=64)
    constexpr int A_T = BM * ROWB;              // 10240
    constexpr int B_T = BN * ROWB;
    constexpr int STG = 2 * A_T + 2 * B_T;
    constexpr int B_CH = (BN * 4) / 256;        // B 16B-chunks per thread (2 or 1)

    extern __shared__ char smem[];
    const uint32_t sbase = smem_u32(smem);
    const int tid = threadIdx.x;
    const int lane = tid & 31, wid = tid >> 5;
    const int wm = wid & 1, wn = wid >> 1;
    const int m0 = blockIdx.y * BM, n0 = blockIdx.x * BN;
    const int nt = K / BK;

    float acc[4][2 * NF16][4];
#pragma unroll
    for (int i = 0; i < 4; i++)
#pragma unroll
        for (int j = 0; j < 2 * NF16; j++)
#pragma unroll
            for (int e = 0; e < 4; e++) acc[i][j][e] = 0.f;

    const uint32_t a_off = (uint32_t)((wm * 64 + (lane & 15)) * ROWB + (lane >> 4) * 16);
    const uint32_t b_off = (uint32_t)((wn * WN + (lane & 7) + ((lane >> 4) & 1) * 8) * ROWB
                                      + ((lane >> 3) & 1) * 16);

    auto issue = [&](int kt) {
        if (kt < nt) {
            const uint32_t sb = sbase + (uint32_t)((kt % NSTG) * STG);
            const size_t kb = (size_t)kt * BK * 2;   // byte offset along K
#pragma unroll
            for (int j = 0; j < 2; j++) {
                int ch = tid + j * 256;
                int r = ch >> 2, c = ch & 3;
                size_t g = (size_t)(m0 + r) * K * 2 + kb + c * 16;
                cp16(sb + r * ROWB + c * 16,        (const char*)Ah + g);
                cp16(sb + A_T + r * ROWB + c * 16,  (const char*)Al + g);
            }
#pragma unroll
            for (int j = 0; j < B_CH; j++) {
                int ch = tid + j * 256;
                int r = ch >> 2, c = ch & 3;
                size_t g = (size_t)(n0 + r) * K * 2 + kb + c * 16;
                cp16(sb + 2 * A_T + r * ROWB + c * 16,       (const char*)Wh + g);
                cp16(sb + 2 * A_T + B_T + r * ROWB + c * 16, (const char*)Wl + g);
            }
        }
        asm volatile("cp.async.commit_group;" ::: "memory");
    };

    auto MMA = [&](int stg) {
        const uint32_t sb = sbase + (uint32_t)(stg * STG);
#pragma unroll
        for (int ks = 0; ks < 2; ks++) {
            uint32_t ah[4][4], al[4][4], bh[NF16][4], bl[NF16][4];
#pragma unroll
            for (int mf = 0; mf < 4; mf++) {
                uint32_t o = sb + a_off + (uint32_t)(mf * 16 * ROWB + ks * 32);
                ldsm4(ah[mf], o);
                ldsm4(al[mf], o + A_T);
            }
#pragma unroll
            for (int g = 0; g < NF16; g++) {
                uint32_t o = sb + b_off + (uint32_t)(g * 16 * ROWB + ks * 32);
                ldsm4(bh[g], o + 2 * A_T);
                ldsm4(bl[g], o + 2 * A_T + B_T);
            }
#pragma unroll
            for (int mf = 0; mf < 4; mf++)
#pragma unroll
                for (int g = 0; g < NF16; g++)
#pragma unroll
                    for (int h = 0; h < 2; h++) {
                        float* c = acc[mf][2 * g + h];
                        mma16816(c, ah[mf], bh[g][2 * h], bh[g][2 * h + 1]);
                        mma16816(c, ah[mf], bl[g][2 * h], bl[g][2 * h + 1]);
                        mma16816(c, al[mf], bh[g][2 * h], bh[g][2 * h + 1]);
                    }
        }
    };

    issue(0); issue(1); issue(2);
    for (int kt = 0; kt < nt; kt++) {
        asm volatile("cp.async.wait_group 2;" ::: "memory");
        __syncthreads();
        MMA(kt % NSTG);
        __syncthreads();
        issue(kt + 3);
    }

    // epilogue
    const int gid = lane >> 2, tig = lane & 3;
#pragma unroll
    for (int mf = 0; mf < 4; mf++) {
        int row = m0 + wm * 64 + mf * 16 + gid;
#pragma unroll
        for (int gn = 0; gn < 2 * NF16; gn++) {
            int col = n0 + wn * WN + gn * 8 + 2 * tig;
#pragma unroll
            for (int half = 0; half < 2; half++) {
                int r = row + half * 8;
                float v0 = acc[mf][gn][2 * half + 0];
                float v1 = acc[mf][gn][2 * half + 1];
                if (EMIT == 0) {
                    *(float2*)&C[(size_t)r * ldc + col] = make_float2(v0, v1);
                } else {
                    __nv_bfloat16 h0 = __float2bfloat16(v0);
                    __nv_bfloat16 h1 = __float2bfloat16(v1);
                    __nv_bfloat16 l0 = __float2bfloat16(v0 - __bfloat162float(h0));
                    __nv_bfloat16 l1 = __float2bfloat16(v1 - __bfloat162float(h1));
                    *(__nv_bfloat162*)&Ch[(size_t)r * ldc + col] = __nv_bfloat162(h0, h1);
                    *(__nv_bfloat162*)&Cl[(size_t)r * ldc + col] = __nv_bfloat162(l0, l1);
                }
            }
        }
    }
}

// ---------------- Prologue: x = pe + cond -> bf16 hi/lo ----------------
__global__ void prologue_kernel(const float* __restrict__ condition,
                                const float* __restrict__ pe,
                                const float* __restrict__ to_cond_w,
                                const float* __restrict__ to_cond_b,
                                __nv_bfloat16* __restrict__ xh,
                                __nv_bfloat16* __restrict__ xl)
{
    int idx = (blockIdx.x * blockDim.x + threadIdx.x) * 2;
    if (idx >= MROWS * D_MODEL) return;
    int d = idx % D_MODEL;
    int l = (idx / D_MODEL) % SEQ;
    int b = idx / (D_MODEL * SEQ);
    float c0 = condition[b] * to_cond_w[d] + to_cond_b[d];
    float c1 = condition[b] * to_cond_w[d + 1] + to_cond_b[d + 1];
    float v0 = pe[l * D_MODEL + d] + c0;
    float v1 = pe[l * D_MODEL + d + 1] + c1;
    uint32_t hv, lv;
    split2(v0, v1, hv, lv);
    *(uint32_t*)((unsigned short*)xh + idx) = hv;
    *(uint32_t*)((unsigned short*)xl + idx) = lv;
}

// ---------------- SIMT NT GEMM (small matmuls) ----------------
template<int BM, int BN, int BK, int TM, int TN, int EPI>
__global__ void gemm_nt(const float* __restrict__ A,
                        const float* __restrict__ W,
                        const float* __restrict__ bias,
                        float* __restrict__ C,
                        int M, int N, int K, int lda, int ldc)
{
    constexpr int TX = BN / TN;
    constexpr int TY = BM / TM;
    constexpr int NT = TX * TY;
    constexpr int KV = BK / 4;

    __shared__ float As[BK][BM + 4];
    __shared__ float Bs[BK][BN + 4];

    const int tid = threadIdx.x;
    const int tx  = tid % TX;
    const int ty  = tid / TX;
    const int n0  = blockIdx.x * BN;
    const int m0  = blockIdx.y * BM;

    const int kChunk = K / gridDim.z;
    const int kBase  = blockIdx.z * kChunk;
    C += (size_t)blockIdx.z * (size_t)M * (size_t)ldc;

    float acc[TM][TN];
#pragma unroll
    for (int i = 0; i < TM; i++)
#pragma unroll
        for (int j = 0; j < TN; j++) acc[i][j] = 0.f;

    for (int kt = 0; kt < kChunk; kt += BK) {
        const int kk = kBase + kt;
        for (int idx = tid; idx < BM * KV; idx += NT) {
            int m  = idx / KV;
            int kv = (idx % KV) * 4;
            const float4 v = *(const float4*)&A[(size_t)(m0 + m) * lda + kk + kv];
            As[kv + 0][m] = v.x; As[kv + 1][m] = v.y;
            As[kv + 2][m] = v.z; As[kv + 3][m] = v.w;
        }
        for (int idx = tid; idx < BN * KV; idx += NT) {
            int n  = idx / KV;
            int kv = (idx % KV) * 4;
            const float4 v = *(const float4*)&W[(size_t)(n0 + n) * K + kk + kv];
            Bs[kv + 0][n] = v.x; Bs[kv + 1][n] = v.y;
            Bs[kv + 2][n] = v.z; Bs[kv + 3][n] = v.w;
        }
        __syncthreads();
#pragma unroll
        for (int k = 0; k < BK; k++) {
            float a[TM], b[TN];
#pragma unroll
            for (int i = 0; i < TM; i++) a[i] = As[k][ty * TM + i];
#pragma unroll
            for (int j = 0; j < TN; j++) b[j] = Bs[k][tx * TN + j];
#pragma unroll
            for (int i = 0; i < TM; i++)
#pragma unroll
                for (int j = 0; j < TN; j++) acc[i][j] = fmaf(a[i], b[j], acc[i][j]);
        }
        __syncthreads();
    }

#pragma unroll
    for (int i = 0; i < TM; i++) {
        int m = m0 + ty * TM + i;
#pragma unroll
        for (int j = 0; j < TN; j++) {
            int n = n0 + tx * TN + j;
            float v = acc[i][j];
            if (EPI == 1) {
                v += bias[n];
                v = fmaxf(v, 0.f) + log1pf(expf(-fabsf(v)));
            }
            C[(size_t)m * ldc + n] = v;
        }
    }
}

// ---------------- Reduce split-K partials for x_proj ----------------
__global__ void reduce_xdbl_kernel()
{
    int idx = blockIdx.x * blockDim.x + threadIdx.x;
    if (idx >= MROWS * XDBL_N) return;
    float s = 0.f;
#pragma unroll
    for (int z = 0; z < SPLITK_XPROJ; z++)
        s += g_xdbl_part[(size_t)z * MROWS * XDBL_N + idx];
    g_xdbl[idx] = s;
}

// ---------------- Depthwise causal conv (width 4) + SiLU ----------------
__global__ void conv_silu_kernel(const float* __restrict__ xz,
                                 const float* __restrict__ cw,
                                 const float* __restrict__ cb,
                                 float* __restrict__ xa_out)
{
    int idx = blockIdx.x * blockDim.x + threadIdx.x;
    if (idx >= MROWS * D_INNER) return;
    int d = idx % D_INNER;
    int l = (idx / D_INNER) % SEQ;
    int b = idx / (D_INNER * SEQ);
    float s = cb[d];
#pragma unroll
    for (int j = 0; j < 4; j++) {
        int ls = l + j - 3;
        if (ls >= 0)
            s += cw[d * 4 + j] * xz[((size_t)(b * SEQ + ls)) * (2 * D_INNER) + d];
    }
    float sig = 1.f / (1.f + expf(-s));
    xa_out[idx] = s * sig;
}

// ---------------- Selective scan + gating -> y bf16 hi/lo ----------------
__global__ void scan_kernel(const float* __restrict__ xz,
                            const float* __restrict__ xa,
                            const float* __restrict__ xdbl,
                            const float* __restrict__ dt,
                            const float* __restrict__ A_log,
                            const float* __restrict__ Dp,
                            __nv_bfloat16* __restrict__ yh,
                            __nv_bfloat16* __restrict__ yl)
{
    const int grp = blockIdx.x;
    const int b   = grp / (D_INNER / 16);
    const int d0  = (grp % (D_INNER / 16)) * 16;
    const int tid = threadIdx.x;
    const int n   = tid & 15;
    const int dl  = tid >> 4;
    const int d   = d0 + dl;

    const float aln = -expf(A_log[d * D_STATE + n]) * 1.44269504088896340736f;
    const float Dv  = Dp[d];

    __shared__ float dt_s[32][16], xa_s[32][16], z_s[32][16], Bm_s[32][16], Cm_s[32][16];

    float h = 0.f;
    for (int l0 = 0; l0 < SEQ; l0 += 32) {
        for (int idx = tid; idx < 32 * 16; idx += 256) {
            int l = idx >> 4, q = idx & 15;
            size_t row = (size_t)(b * SEQ + l0 + l);
            dt_s[l][q] = dt[row * D_INNER + d0 + q];
            xa_s[l][q] = xa[row * D_INNER + d0 + q];
            z_s[l][q]  = xz[row * (2 * D_INNER) + D_INNER + d0 + q];
            Bm_s[l][q] = xdbl[row * XDBL_N + DT_RANK + q];
            Cm_s[l][q] = xdbl[row * XDBL_N + DT_RANK + D_STATE + q];
        }
        __syncthreads();
#pragma unroll 4
        for (int l = 0; l < 32; l++) {
            float dtv = dt_s[l][dl];
            float xav = xa_s[l][dl];
            float da  = exp2f(dtv * aln);
            float bx  = dtv * Bm_s[l][n] * xav;
            h = fmaf(da, h, bx);
            float contrib = h * Cm_s[l][n];
#pragma unroll
            for (int off = 8; off; off >>= 1)
                contrib += __shfl_xor_sync(0xFFFFFFFFu, contrib, off);
            if (n == 0) {
                float zv   = z_s[l][dl];
                float gate = zv / (1.f + expf(-zv));
                float v = (contrib + xav * Dv) * gate;
                size_t o = ((size_t)(b * SEQ + l0 + l)) * D_INNER + d;
                __nv_bfloat16 hb = __float2bfloat16(v);
                yh[o] = hb;
                yl[o] = __float2bfloat16(v - __bfloat162float(hb));
            }
        }
        __syncthreads();
    }
}

// ---------------- Host launch ----------------
extern "C" void kernel_launch(void* const* d_in, const int* in_sizes, int n_in,
                              void* d_out, int out_size)
{
    const float* condition = (const float*)d_in[0];
    const float* pe        = (const float*)d_in[1];
    const float* to_cond_w = (const float*)d_in[2];
    const float* to_cond_b = (const float*)d_in[3];
    const float* in_proj_w = (const float*)d_in[4];
    const float* conv_w    = (const float*)d_in[5];
    const float* conv_b    = (const float*)d_in[6];
    const float* x_proj_w  = (const float*)d_in[7];
    const float* dt_proj_w = (const float*)d_in[8];
    const float* dt_proj_b = (const float*)d_in[9];
    const float* A_log     = (const float*)d_in[10];
    const float* D_skip    = (const float*)d_in[11];
    const float* out_w     = (const float*)d_in[12];
    float* out = (float*)d_out;

    float *pxz, *pxa, *pxdbl, *pxdbl_part, *pdt;
    __nv_bfloat16 *pxh, *pxl, *pyh, *pyl, *pwih, *pwil, *pwoh, *pwol;
    cudaGetSymbolAddress((void**)&pxz, g_xz);
    cudaGetSymbolAddress((void**)&pxa, g_xa);
    cudaGetSymbolAddress((void**)&pxdbl, g_xdbl);
    cudaGetSymbolAddress((void**)&pxdbl_part, g_xdbl_part);
    cudaGetSymbolAddress((void**)&pdt, g_dt);
    cudaGetSymbolAddress((void**)&pxh, g_xh);
    cudaGetSymbolAddress((void**)&pxl, g_xl);
    cudaGetSymbolAddress((void**)&pyh, g_yh);
    cudaGetSymbolAddress((void**)&pyl, g_yl);
    cudaGetSymbolAddress((void**)&pwih, g_wih);
    cudaGetSymbolAddress((void**)&pwil, g_wil);
    cudaGetSymbolAddress((void**)&pwoh, g_woh);
    cudaGetSymbolAddress((void**)&pwol, g_wol);

    // smem: BN=128 -> 3*40960 = 122880; BN=64 -> 3*30720 = 92160
    const int SMEM_128 = 122880, SMEM_64 = 92160;
    cudaFuncSetAttribute(gemm_bf16<128, 0>, cudaFuncAttributeMaxDynamicSharedMemorySize, SMEM_128);
    cudaFuncSetAttribute(gemm_bf16<64, 0>,  cudaFuncAttributeMaxDynamicSharedMemorySize, SMEM_64);
    cudaFuncSetAttribute(gemm_bf16<64, 1>,  cudaFuncAttributeMaxDynamicSharedMemorySize, SMEM_64);

    // prepack weights (every call; graph-capturable)
    {
        int n1 = N_LAYERS * 2 * D_INNER * D_MODEL;   // 16,777,216
        int n2 = N_LAYERS * D_MODEL * D_INNER;       //  8,388,608
        prepack_kernel<<<(n1 / 4 + 255) / 256, 256>>>(in_proj_w, pwih, pwil, n1);
        prepack_kernel<<<(n2 / 4 + 255) / 256, 256>>>(out_w, pwoh, pwol, n2);
    }

    prologue_kernel<<<(MROWS * D_MODEL / 2 + 255) / 256, 256>>>(
        condition, pe, to_cond_w, to_cond_b, pxh, pxl);

    for (int i = 0; i < N_LAYERS; i++) {
        const __nv_bfloat16* wih = pwih + (size_t)i * 2 * D_INNER * D_MODEL;
        const __nv_bfloat16* wil = pwil + (size_t)i * 2 * D_INNER * D_MODEL;
        const __nv_bfloat16* woh = pwoh + (size_t)i * D_MODEL * D_INNER;
        const __nv_bfloat16* wol = pwol + (size_t)i * D_MODEL * D_INNER;
        const float* cwi = conv_w    + (size_t)i * D_INNER * 4;
        const float* cbi = conv_b    + (size_t)i * D_INNER;
        const float* xpi = x_proj_w  + (size_t)i * XDBL_N * D_INNER;
        const float* dpi = dt_proj_w + (size_t)i * D_INNER * DT_RANK;
        const float* dbi = dt_proj_b + (size_t)i * D_INNER;
        const float* ali = A_log     + (size_t)i * D_INNER * D_STATE;
        const float* di  = D_skip    + (size_t)i * D_INNER;

        // 1) in_proj: x(hi/lo) @ W^T -> xz fp32
        gemm_bf16<128, 0><<<dim3(2 * D_INNER / 128, MROWS / 128), 256, SMEM_128>>>(
            pxh, pxl, wih, wil, pxz, nullptr, nullptr, D_MODEL, 2 * D_INNER);

        // 2) depthwise causal conv + silu
        conv_silu_kernel<<<(MROWS * D_INNER + 255) / 256, 256>>>(pxz, cwi, cbi, pxa);

        // 3) x_proj (SIMT split-K 32)
        gemm_nt<64, 96, 16, 4, 6, 0>
            <<<dim3(1, MROWS / 64, SPLITK_XPROJ), 256>>>(
                pxa, xpi, nullptr, pxdbl_part, MROWS, XDBL_N, D_INNER, D_INNER, XDBL_N);
        reduce_xdbl_kernel<<<(MROWS * XDBL_N + 255) / 256, 256>>>();

        // 4) dt_proj + bias + softplus
        gemm_nt<64, 64, 16, 4, 4, 1>
            <<<dim3(D_INNER / 64, MROWS / 64, 1), 256>>>(
                pxdbl, dpi, dbi, pdt, MROWS, D_INNER, DT_RANK, XDBL_N, D_INNER);

        // 5) selective scan + gating -> y hi/lo
        scan_kernel<<<BATCH * (D_INNER / 16), 256>>>(pxz, pxa, pxdbl, pdt, ali, di, pyh, pyl);

        // 6) out_proj: y(hi/lo) @ W^T -> next x (bf16 hi/lo) or final out (fp32)
        if (i == N_LAYERS - 1) {
            gemm_bf16<64, 0><<<dim3(D_MODEL / 64, MROWS / 128), 256, SMEM_64>>>(
                pyh, pyl, woh, wol, out, nullptr, nullptr, D_INNER, D_MODEL);
        } else {
            gemm_bf16<64, 1><<<dim3(D_MODEL / 64, MROWS / 128), 256, SMEM_64>>>(
                pyh, pyl, woh, wol, nullptr, pxh, pxl, D_INNER, D_MODEL);
        }
    }
}

// round 6
// speedup vs baseline: 1.9123x; 1.0894x over previous
#include <cuda_runtime.h>
#include <cuda_bf16.h>
#include <math.h>
#include <stdint.h>

// ---------------- Problem constants ----------------
#define BATCH    2
#define SEQ      512
#define D_MODEL  1024
#define D_INNER  2048
#define D_STATE  16
#define DT_RANK  64
#define N_LAYERS 4
#define MROWS    (BATCH * SEQ)           // 1024
#define XDBL_N   (DT_RANK + 2 * D_STATE) // 96
#define SPLITK_XPROJ 16

// ---------------- Scratch (__device__ globals; no allocation allowed) ----------------
__device__ float g_xz[MROWS * 2 * D_INNER];
__device__ float g_xa[MROWS * D_INNER];
__device__ float g_xdbl[MROWS * XDBL_N];
__device__ float g_xdbl_part[SPLITK_XPROJ * MROWS * XDBL_N];
__device__ float g_dt[MROWS * D_INNER];

// bf16 hi/lo activations
__device__ __nv_bfloat16 g_xh[MROWS * D_MODEL];
__device__ __nv_bfloat16 g_xl[MROWS * D_MODEL];
__device__ __nv_bfloat16 g_yh[MROWS * D_INNER];
__device__ __nv_bfloat16 g_yl[MROWS * D_INNER];
__device__ __nv_bfloat16 g_xah[MROWS * D_INNER];
__device__ __nv_bfloat16 g_xal[MROWS * D_INNER];
__device__ __nv_bfloat16 g_xdh[MROWS * XDBL_N];
__device__ __nv_bfloat16 g_xdl[MROWS * XDBL_N];
// bf16 hi/lo prepacked weights
__device__ __nv_bfloat16 g_wih[N_LAYERS * 2 * D_INNER * D_MODEL];
__device__ __nv_bfloat16 g_wil[N_LAYERS * 2 * D_INNER * D_MODEL];
__device__ __nv_bfloat16 g_woh[N_LAYERS * D_MODEL * D_INNER];
__device__ __nv_bfloat16 g_wol[N_LAYERS * D_MODEL * D_INNER];
__device__ __nv_bfloat16 g_dph[N_LAYERS * D_INNER * DT_RANK];
__device__ __nv_bfloat16 g_dpl[N_LAYERS * D_INNER * DT_RANK];
__device__ __nv_bfloat16 g_xph[N_LAYERS * 128 * D_INNER];   // padded 96->128 rows
__device__ __nv_bfloat16 g_xpl[N_LAYERS * 128 * D_INNER];

// ---------------- helpers ----------------
__device__ __forceinline__ uint32_t smem_u32(const void* p) {
    uint32_t a;
    asm("{ .reg .u64 t; cvta.to.shared.u64 t, %1; cvt.u32.u64 %0, t; }" : "=r"(a) : "l"(p));
    return a;
}
__device__ __forceinline__ void ldsm4(uint32_t* r, uint32_t addr) {
    asm volatile("ldmatrix.sync.aligned.m8n8.x4.shared.b16 {%0,%1,%2,%3}, [%4];"
                 : "=r"(r[0]), "=r"(r[1]), "=r"(r[2]), "=r"(r[3]) : "r"(addr));
}
__device__ __forceinline__ void mma16816(float* c, const uint32_t* a, uint32_t b0, uint32_t b1) {
    asm volatile("mma.sync.aligned.m16n8k16.row.col.f32.bf16.bf16.f32 "
                 "{%0,%1,%2,%3}, {%4,%5,%6,%7}, {%8,%9}, {%0,%1,%2,%3};"
                 : "+f"(c[0]), "+f"(c[1]), "+f"(c[2]), "+f"(c[3])
                 : "r"(a[0]), "r"(a[1]), "r"(a[2]), "r"(a[3]), "r"(b0), "r"(b1));
}
__device__ __forceinline__ void cp16(uint32_t dst, const void* src) {
    asm volatile("cp.async.cg.shared.global [%0], [%1], 16;" :: "r"(dst), "l"(src));
}
__device__ __forceinline__ void split2(float v0, float v1, uint32_t& hi, uint32_t& lo) {
    __nv_bfloat16 h0 = __float2bfloat16(v0);
    __nv_bfloat16 h1 = __float2bfloat16(v1);
    __nv_bfloat16 l0 = __float2bfloat16(v0 - __bfloat162float(h0));
    __nv_bfloat16 l1 = __float2bfloat16(v1 - __bfloat162float(h1));
    hi = (uint32_t)*(unsigned short*)&h0 | ((uint32_t)*(unsigned short*)&h1 << 16);
    lo = (uint32_t)*(unsigned short*)&l0 | ((uint32_t)*(unsigned short*)&l1 << 16);
}

// ---------------- Weight prepack: fp32 -> bf16 hi/lo ----------------
__global__ void prepack_kernel(const float* __restrict__ src,
                               __nv_bfloat16* __restrict__ hi,
                               __nv_bfloat16* __restrict__ lo, int n)
{
    int i = (blockIdx.x * blockDim.x + threadIdx.x) * 4;
    if (i >= n) return;
    float4 f = *(const float4*)(src + i);
    uint2 hv, lv;
    split2(f.x, f.y, hv.x, lv.x);
    split2(f.z, f.w, hv.y, lv.y);
    *(uint2*)((unsigned short*)hi + i) = hv;
    *(uint2*)((unsigned short*)lo + i) = lv;
}

// Prepack x_proj weights, padding rows 96->128 with zeros.
// src [L][96][2048] -> dst [L][128][2048]
__global__ void prepack_pad_kernel(const float* __restrict__ src,
                                   __nv_bfloat16* __restrict__ hi,
                                   __nv_bfloat16* __restrict__ lo)
{
    int i = (blockIdx.x * blockDim.x + threadIdx.x) * 2;   // over L*128*2048
    if (i >= N_LAYERS * 128 * D_INNER) return;
    int k = i % D_INNER;
    int r = (i / D_INNER) % 128;
    int lyr = i / (128 * D_INNER);
    float v0 = 0.f, v1 = 0.f;
    if (r < XDBL_N) {
        const float* s = src + ((size_t)lyr * XDBL_N + r) * D_INNER + k;
        v0 = s[0]; v1 = s[1];
    }
    uint32_t hv, lv;
    split2(v0, v1, hv, lv);
    *(uint32_t*)((unsigned short*)hi + i) = hv;
    *(uint32_t*)((unsigned short*)lo + i) = lv;
}

// ============================================================
// bf16-split NT GEMM via mma.sync + 2-stage cp.async, 2 CTA/SM.
// C[m,n] = sum_k A[m,k]*W[n,k]; A,W prepacked bf16 hi/lo.
// EMIT: 0 = fp32 C, 1 = bf16 hi/lo C, 2 = softplus(C+bias) fp32.
// Split-K via gridDim.z (partials stacked: C += z*M*ldc).
// ============================================================
template<int BM, int BN, int EMIT>
__global__ void __launch_bounds__(256, 2)
gemm2(const __nv_bfloat16* __restrict__ Ah, const __nv_bfloat16* __restrict__ Al,
      const __nv_bfloat16* __restrict__ Wh, const __nv_bfloat16* __restrict__ Wl,
      const float* __restrict__ bias,
      float* __restrict__ C, __nv_bfloat16* __restrict__ Ch, __nv_bfloat16* __restrict__ Cl,
      int M, int Ktot, int lda, int ldw, int ldc, int nmax)
{
    constexpr int ROWB = 80;
    constexpr int MF   = BM / 32;          // m16 frags per warp (2 or 4)
    constexpr int WN   = BN / 4;           // warp n extent
    constexpr int NF16 = WN / 16;          // 1 or 2
    constexpr int A_T  = BM * ROWB;
    constexpr int B_T  = BN * ROWB;
    constexpr int STG  = 2 * (A_T + B_T);
    constexpr int A_CH = BM * 4 / 256;     // 16B chunks per thread
    constexpr int B_CH = BN * 4 / 256;

    extern __shared__ char smem[];
    const uint32_t sbase = smem_u32(smem);
    const int tid = threadIdx.x;
    const int lane = tid & 31, wid = tid >> 5;
    const int wm = wid & 1, wn = wid >> 1;
    const int m0 = blockIdx.y * BM, n0 = blockIdx.x * BN;

    const int kchunk = Ktot / gridDim.z;
    const int kbase  = blockIdx.z * kchunk;
    const int nt     = kchunk / 32;
    C += (size_t)blockIdx.z * (size_t)M * (size_t)ldc;

    float acc[MF][2 * NF16][4];
#pragma unroll
    for (int i = 0; i < MF; i++)
#pragma unroll
        for (int j = 0; j < 2 * NF16; j++)
#pragma unroll
            for (int e = 0; e < 4; e++) acc[i][j][e] = 0.f;

    const uint32_t a_off = (uint32_t)((wm * (BM / 2) + (lane & 15)) * ROWB + (lane >> 4) * 16);
    const uint32_t b_off = (uint32_t)((wn * WN + (lane & 7) + ((lane >> 4) & 1) * 8) * ROWB
                                      + ((lane >> 3) & 1) * 16);

    auto issue = [&](int kt) {
        if (kt < nt) {
            const uint32_t sb = sbase + (uint32_t)((kt & 1) * STG);
            const size_t kb = ((size_t)kbase + (size_t)kt * 32) * 2;   // bytes
#pragma unroll
            for (int j = 0; j < A_CH; j++) {
                int ch = tid + j * 256;
                int r = ch >> 2, c = ch & 3;
                size_t g = (size_t)(m0 + r) * lda * 2 + kb + c * 16;
                cp16(sb + r * ROWB + c * 16,       (const char*)Ah + g);
                cp16(sb + A_T + r * ROWB + c * 16, (const char*)Al + g);
            }
#pragma unroll
            for (int j = 0; j < B_CH; j++) {
                int ch = tid + j * 256;
                int r = ch >> 2, c = ch & 3;
                size_t g = (size_t)(n0 + r) * ldw * 2 + kb + c * 16;
                cp16(sb + 2 * A_T + r * ROWB + c * 16,       (const char*)Wh + g);
                cp16(sb + 2 * A_T + B_T + r * ROWB + c * 16, (const char*)Wl + g);
            }
        }
        asm volatile("cp.async.commit_group;" ::: "memory");
    };

    auto MMA = [&](int stg) {
        const uint32_t sb = sbase + (uint32_t)(stg * STG);
#pragma unroll
        for (int ks = 0; ks < 2; ks++) {
            uint32_t bh[NF16][4], bl[NF16][4];
#pragma unroll
            for (int g = 0; g < NF16; g++) {
                uint32_t o = sb + b_off + (uint32_t)(g * 16 * ROWB + ks * 32);
                ldsm4(bh[g], o + 2 * A_T);
                ldsm4(bl[g], o + 2 * A_T + B_T);
            }
#pragma unroll
            for (int mf = 0; mf < MF; mf++) {
                uint32_t ah[4], al[4];
                uint32_t o = sb + a_off + (uint32_t)(mf * 16 * ROWB + ks * 32);
                ldsm4(ah, o);
                ldsm4(al, o + A_T);
#pragma unroll
                for (int g = 0; g < NF16; g++)
#pragma unroll
                    for (int h = 0; h < 2; h++) {
                        float* c = acc[mf][2 * g + h];
                        mma16816(c, ah, bh[g][2 * h], bh[g][2 * h + 1]);
                        mma16816(c, ah, bl[g][2 * h], bl[g][2 * h + 1]);
                        mma16816(c, al, bh[g][2 * h], bh[g][2 * h + 1]);
                    }
            }
        }
    };

    issue(0); issue(1);
    for (int kt = 0; kt < nt; kt++) {
        asm volatile("cp.async.wait_group 1;" ::: "memory");
        __syncthreads();
        MMA(kt & 1);
        __syncthreads();
        issue(kt + 2);
    }

    // epilogue
    const int gid = lane >> 2, tig = lane & 3;
#pragma unroll
    for (int mf = 0; mf < MF; mf++) {
        int row = m0 + wm * (BM / 2) + mf * 16 + gid;
#pragma unroll
        for (int gn = 0; gn < 2 * NF16; gn++) {
            int col = n0 + wn * WN + gn * 8 + 2 * tig;
            if (col >= nmax) continue;
#pragma unroll
            for (int half = 0; half < 2; half++) {
                int r = row + half * 8;
                float v0 = acc[mf][gn][2 * half + 0];
                float v1 = acc[mf][gn][2 * half + 1];
                if (EMIT == 0) {
                    *(float2*)&C[(size_t)r * ldc + col] = make_float2(v0, v1);
                } else if (EMIT == 1) {
                    __nv_bfloat16 h0 = __float2bfloat16(v0);
                    __nv_bfloat16 h1 = __float2bfloat16(v1);
                    __nv_bfloat16 l0 = __float2bfloat16(v0 - __bfloat162float(h0));
                    __nv_bfloat16 l1 = __float2bfloat16(v1 - __bfloat162float(h1));
                    *(__nv_bfloat162*)&Ch[(size_t)r * ldc + col] = __nv_bfloat162(h0, h1);
                    *(__nv_bfloat162*)&Cl[(size_t)r * ldc + col] = __nv_bfloat162(l0, l1);
                } else {
                    v0 += bias[col];
                    v1 += bias[col + 1];
                    v0 = fmaxf(v0, 0.f) + log1pf(expf(-fabsf(v0)));
                    v1 = fmaxf(v1, 0.f) + log1pf(expf(-fabsf(v1)));
                    *(float2*)&C[(size_t)r * ldc + col] = make_float2(v0, v1);
                }
            }
        }
    }
}

// ---------------- Prologue: x = pe + cond -> bf16 hi/lo ----------------
__global__ void prologue_kernel(const float* __restrict__ condition,
                                const float* __restrict__ pe,
                                const float* __restrict__ to_cond_w,
                                const float* __restrict__ to_cond_b,
                                __nv_bfloat16* __restrict__ xh,
                                __nv_bfloat16* __restrict__ xl)
{
    int idx = (blockIdx.x * blockDim.x + threadIdx.x) * 2;
    if (idx >= MROWS * D_MODEL) return;
    int d = idx % D_MODEL;
    int l = (idx / D_MODEL) % SEQ;
    int b = idx / (D_MODEL * SEQ);
    float c0 = condition[b] * to_cond_w[d] + to_cond_b[d];
    float c1 = condition[b] * to_cond_w[d + 1] + to_cond_b[d + 1];
    float v0 = pe[l * D_MODEL + d] + c0;
    float v1 = pe[l * D_MODEL + d + 1] + c1;
    uint32_t hv, lv;
    split2(v0, v1, hv, lv);
    *(uint32_t*)((unsigned short*)xh + idx) = hv;
    *(uint32_t*)((unsigned short*)xl + idx) = lv;
}

// ---------------- Reduce split-K partials; emit fp32 + bf16 hi/lo ----------------
__global__ void reduce_xdbl_kernel()
{
    int idx = (blockIdx.x * blockDim.x + threadIdx.x) * 2;
    if (idx >= MROWS * XDBL_N) return;
    float s0 = 0.f, s1 = 0.f;
#pragma unroll
    for (int z = 0; z < SPLITK_XPROJ; z++) {
        const float* p = &g_xdbl_part[(size_t)z * MROWS * XDBL_N + idx];
        s0 += p[0]; s1 += p[1];
    }
    g_xdbl[idx] = s0;
    g_xdbl[idx + 1] = s1;
    uint32_t hv, lv;
    split2(s0, s1, hv, lv);
    *(uint32_t*)((unsigned short*)g_xdh + idx) = hv;
    *(uint32_t*)((unsigned short*)g_xdl + idx) = lv;
}

// ---------------- Depthwise causal conv (width 4) + SiLU -> fp32 + hi/lo ----------------
__global__ void conv_silu_kernel(const float* __restrict__ xz,
                                 const float* __restrict__ cw,
                                 const float* __restrict__ cb,
                                 float* __restrict__ xa_out,
                                 __nv_bfloat16* __restrict__ xah,
                                 __nv_bfloat16* __restrict__ xal)
{
    int idx = blockIdx.x * blockDim.x + threadIdx.x;
    if (idx >= MROWS * D_INNER) return;
    int d = idx % D_INNER;
    int l = (idx / D_INNER) % SEQ;
    int b = idx / (D_INNER * SEQ);
    float s = cb[d];
#pragma unroll
    for (int j = 0; j < 4; j++) {
        int ls = l + j - 3;
        if (ls >= 0)
            s += cw[d * 4 + j] * xz[((size_t)(b * SEQ + ls)) * (2 * D_INNER) + d];
    }
    float sig = 1.f / (1.f + expf(-s));
    float v = s * sig;
    xa_out[idx] = v;
    __nv_bfloat16 hb = __float2bfloat16(v);
    xah[idx] = hb;
    xal[idx] = __float2bfloat16(v - __bfloat162float(hb));
}

// ---------------- Selective scan + gating -> y bf16 hi/lo ----------------
__global__ void scan_kernel(const float* __restrict__ xz,
                            const float* __restrict__ xa,
                            const float* __restrict__ xdbl,
                            const float* __restrict__ dt,
                            const float* __restrict__ A_log,
                            const float* __restrict__ Dp,
                            __nv_bfloat16* __restrict__ yh,
                            __nv_bfloat16* __restrict__ yl)
{
    const int grp = blockIdx.x;
    const int b   = grp / (D_INNER / 16);
    const int d0  = (grp % (D_INNER / 16)) * 16;
    const int tid = threadIdx.x;
    const int n   = tid & 15;
    const int dl  = tid >> 4;
    const int d   = d0 + dl;

    const float aln = -expf(A_log[d * D_STATE + n]) * 1.44269504088896340736f;
    const float Dv  = Dp[d];

    __shared__ float dt_s[32][16], xa_s[32][16], z_s[32][16], Bm_s[32][16], Cm_s[32][16];

    float h = 0.f;
    for (int l0 = 0; l0 < SEQ; l0 += 32) {
        for (int idx = tid; idx < 32 * 16; idx += 256) {
            int l = idx >> 4, q = idx & 15;
            size_t row = (size_t)(b * SEQ + l0 + l);
            dt_s[l][q] = dt[row * D_INNER + d0 + q];
            xa_s[l][q] = xa[row * D_INNER + d0 + q];
            z_s[l][q]  = xz[row * (2 * D_INNER) + D_INNER + d0 + q];
            Bm_s[l][q] = xdbl[row * XDBL_N + DT_RANK + q];
            Cm_s[l][q] = xdbl[row * XDBL_N + DT_RANK + D_STATE + q];
        }
        __syncthreads();
#pragma unroll 4
        for (int l = 0; l < 32; l++) {
            float dtv = dt_s[l][dl];
            float xav = xa_s[l][dl];
            float da  = exp2f(dtv * aln);
            float bx  = dtv * Bm_s[l][n] * xav;
            h = fmaf(da, h, bx);
            float contrib = h * Cm_s[l][n];
#pragma unroll
            for (int off = 8; off; off >>= 1)
                contrib += __shfl_xor_sync(0xFFFFFFFFu, contrib, off);
            if (n == 0) {
                float zv   = z_s[l][dl];
                float gate = zv / (1.f + expf(-zv));
                float v = (contrib + xav * Dv) * gate;
                size_t o = ((size_t)(b * SEQ + l0 + l)) * D_INNER + d;
                __nv_bfloat16 hb = __float2bfloat16(v);
                yh[o] = hb;
                yl[o] = __float2bfloat16(v - __bfloat162float(hb));
            }
        }
        __syncthreads();
    }
}

// ---------------- Host launch ----------------
extern "C" void kernel_launch(void* const* d_in, const int* in_sizes, int n_in,
                              void* d_out, int out_size)
{
    const float* condition = (const float*)d_in[0];
    const float* pe        = (const float*)d_in[1];
    const float* to_cond_w = (const float*)d_in[2];
    const float* to_cond_b = (const float*)d_in[3];
    const float* in_proj_w = (const float*)d_in[4];
    const float* conv_w    = (const float*)d_in[5];
    const float* conv_b    = (const float*)d_in[6];
    const float* x_proj_w  = (const float*)d_in[7];
    const float* dt_proj_w = (const float*)d_in[8];
    const float* dt_proj_b = (const float*)d_in[9];
    const float* A_log     = (const float*)d_in[10];
    const float* D_skip    = (const float*)d_in[11];
    const float* out_w     = (const float*)d_in[12];
    float* out = (float*)d_out;

    float *pxz, *pxa, *pxdbl, *pxdbl_part, *pdt;
    __nv_bfloat16 *pxh, *pxl, *pyh, *pyl, *pxah, *pxal, *pxdh, *pxdl;
    __nv_bfloat16 *pwih, *pwil, *pwoh, *pwol, *pdph, *pdpl, *pxph, *pxpl;
    cudaGetSymbolAddress((void**)&pxz, g_xz);
    cudaGetSymbolAddress((void**)&pxa, g_xa);
    cudaGetSymbolAddress((void**)&pxdbl, g_xdbl);
    cudaGetSymbolAddress((void**)&pxdbl_part, g_xdbl_part);
    cudaGetSymbolAddress((void**)&pdt, g_dt);
    cudaGetSymbolAddress((void**)&pxh, g_xh);
    cudaGetSymbolAddress((void**)&pxl, g_xl);
    cudaGetSymbolAddress((void**)&pyh, g_yh);
    cudaGetSymbolAddress((void**)&pyl, g_yl);
    cudaGetSymbolAddress((void**)&pxah, g_xah);
    cudaGetSymbolAddress((void**)&pxal, g_xal);
    cudaGetSymbolAddress((void**)&pxdh, g_xdh);
    cudaGetSymbolAddress((void**)&pxdl, g_xdl);
    cudaGetSymbolAddress((void**)&pwih, g_wih);
    cudaGetSymbolAddress((void**)&pwil, g_wil);
    cudaGetSymbolAddress((void**)&pwoh, g_woh);
    cudaGetSymbolAddress((void**)&pwol, g_wol);
    cudaGetSymbolAddress((void**)&pdph, g_dph);
    cudaGetSymbolAddress((void**)&pdpl, g_dpl);
    cudaGetSymbolAddress((void**)&pxph, g_xph);
    cudaGetSymbolAddress((void**)&pxpl, g_xpl);

    // dynamic smem per config (2-stage)
    const int SM_128_128 = 2 * (2 * 128 * 80 + 2 * 128 * 80);   // 81920
    const int SM_64_128  = 2 * (2 * 64 * 80 + 2 * 128 * 80);    // 61440
    const int SM_64_64   = 2 * (2 * 64 * 80 + 2 * 64 * 80);     // 40960
    cudaFuncSetAttribute((const void*)gemm2<128, 128, 0>, cudaFuncAttributeMaxDynamicSharedMemorySize, SM_128_128);
    cudaFuncSetAttribute((const void*)gemm2<64, 128, 0>,  cudaFuncAttributeMaxDynamicSharedMemorySize, SM_64_128);
    cudaFuncSetAttribute((const void*)gemm2<64, 128, 2>,  cudaFuncAttributeMaxDynamicSharedMemorySize, SM_64_128);
    cudaFuncSetAttribute((const void*)gemm2<64, 64, 0>,   cudaFuncAttributeMaxDynamicSharedMemorySize, SM_64_64);
    cudaFuncSetAttribute((const void*)gemm2<64, 64, 1>,   cudaFuncAttributeMaxDynamicSharedMemorySize, SM_64_64);

    // prepack weights
    {
        int n1 = N_LAYERS * 2 * D_INNER * D_MODEL;
        int n2 = N_LAYERS * D_MODEL * D_INNER;
        int n3 = N_LAYERS * D_INNER * DT_RANK;
        prepack_kernel<<<(n1 / 4 + 255) / 256, 256>>>(in_proj_w, pwih, pwil, n1);
        prepack_kernel<<<(n2 / 4 + 255) / 256, 256>>>(out_w, pwoh, pwol, n2);
        prepack_kernel<<<(n3 / 4 + 255) / 256, 256>>>(dt_proj_w, pdph, pdpl, n3);
        int n4 = N_LAYERS * 128 * D_INNER;
        prepack_pad_kernel<<<(n4 / 2 + 255) / 256, 256>>>(x_proj_w, pxph, pxpl);
    }

    prologue_kernel<<<(MROWS * D_MODEL / 2 + 255) / 256, 256>>>(
        condition, pe, to_cond_w, to_cond_b, pxh, pxl);

    for (int i = 0; i < N_LAYERS; i++) {
        const __nv_bfloat16* wih = pwih + (size_t)i * 2 * D_INNER * D_MODEL;
        const __nv_bfloat16* wil = pwil + (size_t)i * 2 * D_INNER * D_MODEL;
        const __nv_bfloat16* woh = pwoh + (size_t)i * D_MODEL * D_INNER;
        const __nv_bfloat16* wol = pwol + (size_t)i * D_MODEL * D_INNER;
        const __nv_bfloat16* dph = pdph + (size_t)i * D_INNER * DT_RANK;
        const __nv_bfloat16* dpl = pdpl + (size_t)i * D_INNER * DT_RANK;
        const __nv_bfloat16* xph = pxph + (size_t)i * 128 * D_INNER;
        const __nv_bfloat16* xpl = pxpl + (size_t)i * 128 * D_INNER;
        const float* cwi = conv_w    + (size_t)i * D_INNER * 4;
        const float* cbi = conv_b    + (size_t)i * D_INNER;
        const float* dbi = dt_proj_b + (size_t)i * D_INNER;
        const float* ali = A_log     + (size_t)i * D_INNER * D_STATE;
        const float* di  = D_skip    + (size_t)i * D_INNER;

        // 1) in_proj: [1024,1024] x [4096,1024]^T -> xz fp32   (256 CTAs)
        gemm2<128, 128, 0><<<dim3(2 * D_INNER / 128, MROWS / 128, 1), 256, SM_128_128>>>(
            pxh, pxl, wih, wil, nullptr, pxz, nullptr, nullptr,
            MROWS, D_MODEL, D_MODEL, D_MODEL, 2 * D_INNER, 2 * D_INNER);

        // 2) depthwise conv + silu -> xa fp32 + hi/lo
        conv_silu_kernel<<<(MROWS * D_INNER + 255) / 256, 256>>>(pxz, cwi, cbi, pxa, pxah, pxal);

        // 3) x_proj split-K z=16 -> partials fp32 (256 CTAs), then reduce -> xdbl + hi/lo
        gemm2<64, 128, 0><<<dim3(1, MROWS / 64, SPLITK_XPROJ), 256, SM_64_128>>>(
            pxah, pxal, xph, xpl, nullptr, pxdbl_part, nullptr, nullptr,
            MROWS, D_INNER, D_INNER, D_INNER, XDBL_N, XDBL_N);
        reduce_xdbl_kernel<<<(MROWS * XDBL_N / 2 + 255) / 256, 256>>>();

        // 4) dt_proj + bias + softplus -> dt fp32   (256 CTAs)
        gemm2<64, 128, 2><<<dim3(D_INNER / 128, MROWS / 64, 1), 256, SM_64_128>>>(
            pxdh, pxdl, dph, dpl, dbi, pdt, nullptr, nullptr,
            MROWS, DT_RANK, XDBL_N, DT_RANK, D_INNER, D_INNER);

        // 5) selective scan + gating -> y hi/lo
        scan_kernel<<<BATCH * (D_INNER / 16), 256>>>(pxz, pxa, pxdbl, pdt, ali, di, pyh, pyl);

        // 6) out_proj: [1024,2048] x [1024,2048]^T   (256 CTAs)
        if (i == N_LAYERS - 1) {
            gemm2<64, 64, 0><<<dim3(D_MODEL / 64, MROWS / 64, 1), 256, SM_64_64>>>(
                pyh, pyl, woh, wol, nullptr, out, nullptr, nullptr,
                MROWS, D_INNER, D_INNER, D_INNER, D_MODEL, D_MODEL);
        } else {
            gemm2<64, 64, 1><<<dim3(D_MODEL / 64, MROWS / 64, 1), 256, SM_64_64>>>(
                pyh, pyl, woh, wol, nullptr, nullptr, pxh, pxl,
                MROWS, D_INNER, D_INNER, D_INNER, D_MODEL, D_MODEL);
        }
    }
}